// round 16
// baseline (speedup 1.0000x reference)
#include <cuda_runtime.h>
#include <cuda_fp16.h>
#include <math.h>
#include <stdint.h>

#define T_SEQ   2048
#define BATCH   2
#define DMODEL  1024
#define NHEADS  16
#define DHEAD   64
#define MROWS   (BATCH * T_SEQ)   // 4096
#define PI_F    3.14159265358979323846f

// ---------------- device scratch (fp16 end-to-end dataflow) --------------
__device__ __half g_xh [MROWS * DMODEL];   // x hi
__device__ __half g_xl [MROWS * DMODEL];   // x lo (residual)
__device__ __half g_wqh[DMODEL * DMODEL];  // weights hi only
__device__ __half g_wkh[DMODEL * DMODEL];
__device__ __half g_wvh[DMODEL * DMODEL];
__device__ __half g_weh[DMODEL * DMODEL];
__device__ __half g_qh [MROWS * DMODEL];   // q*0.125 hi
__device__ __half g_ql [MROWS * DMODEL];   // q*0.125 lo
__device__ __half g_kh [MROWS * DMODEL];   // k hi
__device__ __half g_vt [BATCH * NHEADS * DHEAD * T_SEQ];  // v hi, transposed [b][h][dh][t]
__device__ __half g_aoh[MROWS * DMODEL];   // attention out hi
__device__ __half g_aol[MROWS * DMODEL];   // attention out lo

// =========================================================================
// helpers
// =========================================================================
__device__ __forceinline__ uint32_t smem_u32(const void* p) {
    uint32_t a;
    asm("{ .reg .u64 t; cvta.to.shared.u64 t, %1; cvt.u32.u64 %0, t; }"
        : "=r"(a) : "l"(p));
    return a;
}

// swizzled byte offset of the 16B quad holding (row, half-of-16-k) in a
// [rows][16] fp16 chunk; 8 rows of any ldmatrix 8x8 matrix hit 8 bank groups.
__device__ __forceinline__ uint32_t qoff(int row, int half) {
    return (uint32_t)((((row >> 3) << 4) + ((row & 7) << 1) +
                       (half ^ ((row >> 2) & 1))) << 4);
}

#define LDM4(r, addr) \
    asm volatile("ldmatrix.sync.aligned.m8n8.x4.shared.b16 {%0,%1,%2,%3}, [%4];" \
        : "=r"((r)[0]), "=r"((r)[1]), "=r"((r)[2]), "=r"((r)[3]) : "r"(addr))

#define MMA_F16(d, a, b0_, b1_) \
    asm volatile("mma.sync.aligned.m16n8k16.row.col.f32.f16.f16.f32 " \
        "{%0,%1,%2,%3},{%4,%5,%6,%7},{%8,%9},{%0,%1,%2,%3};" \
        : "+f"((d)[0]), "+f"((d)[1]), "+f"((d)[2]), "+f"((d)[3]) \
        : "r"((a)[0]), "r"((a)[1]), "r"((a)[2]), "r"((a)[3]), \
          "r"(b0_), "r"(b1_))

// fp32x4 -> fp16 hi + fp16 lo(residual), packed as uint2
__device__ __forceinline__ void cvt_hilo(float4 v, uint2& hi, uint2& lo) {
    __half2 h01 = __floats2half2_rn(v.x, v.y);
    __half2 h23 = __floats2half2_rn(v.z, v.w);
    float2 f01 = __half22float2(h01);
    float2 f23 = __half22float2(h23);
    __half2 l01 = __floats2half2_rn(v.x - f01.x, v.y - f01.y);
    __half2 l23 = __floats2half2_rn(v.z - f23.x, v.w - f23.y);
    hi.x = *reinterpret_cast<unsigned*>(&h01);
    hi.y = *reinterpret_cast<unsigned*>(&h23);
    lo.x = *reinterpret_cast<unsigned*>(&l01);
    lo.y = *reinterpret_cast<unsigned*>(&l23);
}

__device__ __forceinline__ uint2 cvt_hi(float4 v) {
    __half2 h01 = __floats2half2_rn(v.x, v.y);
    __half2 h23 = __floats2half2_rn(v.z, v.w);
    uint2 hi;
    hi.x = *reinterpret_cast<unsigned*>(&h01);
    hi.y = *reinterpret_cast<unsigned*>(&h23);
    return hi;
}

// two fp32 -> packed fp16x2 hi + fp16x2 lo(residual)
__device__ __forceinline__ uint32_t pk_hilo(float a, float b, uint32_t& lo) {
    __half2 h = __floats2half2_rn(a, b);
    float2 f = __half22float2(h);
    __half2 l = __floats2half2_rn(a - f.x, b - f.y);
    lo = *reinterpret_cast<uint32_t*>(&l);
    return *reinterpret_cast<uint32_t*>(&h);
}

// =========================================================================
// one-time fp32 -> fp16 conversion (memory-bound, ~10 us)
// =========================================================================
__global__ __launch_bounds__(256)
void preconvert(const float* __restrict__ x,  const float* __restrict__ wq,
                const float* __restrict__ wk, const float* __restrict__ wv,
                const float* __restrict__ we)
{
    const int gt = blockIdx.x * 256 + threadIdx.x;
    const int G  = gridDim.x * 256;
    const int NX = MROWS * DMODEL / 4;
    for (int i = gt; i < NX; i += G) {
        uint2 hi, lo;
        cvt_hilo(((const float4*)x)[i], hi, lo);
        ((uint2*)g_xh)[i] = hi;
        ((uint2*)g_xl)[i] = lo;
    }
    const int NW = DMODEL * DMODEL / 4;
    for (int i = gt; i < NW; i += G) {
        ((uint2*)g_wqh)[i] = cvt_hi(((const float4*)wq)[i]);
        ((uint2*)g_wkh)[i] = cvt_hi(((const float4*)wk)[i]);
        ((uint2*)g_wvh)[i] = cvt_hi(((const float4*)wv)[i]);
        ((uint2*)g_weh)[i] = cvt_hi(((const float4*)we)[i]);
    }
}

// =========================================================================
// fp16 2-term GEMM (NT): C = Ah*Bh + Al*Bh, all-fp16 inputs, BK=32,
// double-buffered register prefetch, ONE barrier per 64 MMAs/warp.
// mode 0: QKV (z selects W + epilogue: Q->qh/ql scaled, K->kh, V->vt^T)
// mode 1: out-projection (fp32 C)
// =========================================================================
#define GEMM_SMEM 49152   // 2 buffers x (Ah 8K | Al 8K | Bh 8K)

__global__ __launch_bounds__(256)
void gemm_h(const __half* __restrict__ Ah, const __half* __restrict__ Al,
            const __half* __restrict__ B0, const __half* __restrict__ B1,
            const __half* __restrict__ B2, float* __restrict__ Cout, int mode)
{
    extern __shared__ __align__(16) char gsm[];

    const __half* Bh = (blockIdx.z == 0) ? B0 : (blockIdx.z == 1) ? B1 : B2;

    const int tid  = threadIdx.x;
    const int warp = tid >> 5;
    const int lane = tid & 31;
    const int wm   = (warp & 3) << 5;
    const int wn   = (warp >> 2) << 6;
    const int bm   = blockIdx.y << 7;
    const int bn   = blockIdx.x << 7;

    // staging: 2 quads per matrix per thread; idx = tid (+256): row=idx>>2, q4=idx&3
    const int r0s = tid >> 2;
    const int q4s = tid & 3;
    const uint32_t sd0 = ((uint32_t)(q4s >> 1) << 12) + qoff(r0s,      q4s & 1);
    const uint32_t sd1 = ((uint32_t)(q4s >> 1) << 12) + qoff(r0s + 64, q4s & 1);

    const __half* pA0 = Ah + (size_t)(bm + r0s) * DMODEL + q4s * 8;
    const __half* pA1 = pA0 + 64 * DMODEL;
    const __half* pL0 = Al + (size_t)(bm + r0s) * DMODEL + q4s * 8;
    const __half* pL1 = pL0 + 64 * DMODEL;
    const __half* pB0 = Bh + (size_t)(bn + r0s) * DMODEL + q4s * 8;
    const __half* pB1 = pB0 + 64 * DMODEL;

    const uint32_t sb = smem_u32(gsm);
    uint32_t aOff[2], bOff[4];
    {
        int r  = (lane & 7) + ((lane >> 3) & 1) * 8;
        int hA = (lane >> 4) & 1;
        aOff[0] = qoff(wm + r,      hA);
        aOff[1] = qoff(wm + 16 + r, hA);
        int rn_ = (lane & 7) + ((lane >> 4) & 1) * 8;
        int hB  = (lane >> 3) & 1;
#pragma unroll
        for (int j = 0; j < 4; j++)
            bOff[j] = qoff(wn + 16 * j + rn_, hB);
    }

    float acc[2][8][4];
#pragma unroll
    for (int i = 0; i < 2; i++)
#pragma unroll
        for (int j = 0; j < 8; j++)
#pragma unroll
            for (int e = 0; e < 4; e++) acc[i][j][e] = 0.f;

    // ---- stage chunk 0 into buffer 0 ----
    {
        *(uint4*)(gsm + sd0)           = *(const uint4*)pA0;
        *(uint4*)(gsm + sd1)           = *(const uint4*)pA1;
        *(uint4*)(gsm + 8192 + sd0)    = *(const uint4*)pL0;
        *(uint4*)(gsm + 8192 + sd1)    = *(const uint4*)pL1;
        *(uint4*)(gsm + 16384 + sd0)   = *(const uint4*)pB0;
        *(uint4*)(gsm + 16384 + sd1)   = *(const uint4*)pB1;
    }
    __syncthreads();

    for (int c = 0; c < DMODEL / 32; c++) {
        const uint32_t bo = (uint32_t)(c & 1) * 24576u;
        const uint32_t so = bo ^ 24576u;
        const bool pf = (c < DMODEL / 32 - 1);

        uint4 va0, va1, vl0, vl1, vb0, vb1;
        if (pf) {
            pA0 += 32; pA1 += 32; pL0 += 32; pL1 += 32; pB0 += 32; pB1 += 32;
            va0 = *(const uint4*)pA0;  va1 = *(const uint4*)pA1;
            vl0 = *(const uint4*)pL0;  vl1 = *(const uint4*)pL1;
            vb0 = *(const uint4*)pB0;  vb1 = *(const uint4*)pB1;
        }

#pragma unroll
        for (int s = 0; s < 2; s++) {
            const uint32_t cb = sb + bo + ((uint32_t)s << 12);
            uint32_t Ahf[2][4], Alf[2][4], Bhf[4][4];
            LDM4(Ahf[0], cb + aOff[0]);          LDM4(Ahf[1], cb + aOff[1]);
            LDM4(Alf[0], cb + 8192 + aOff[0]);   LDM4(Alf[1], cb + 8192 + aOff[1]);
#pragma unroll
            for (int g = 0; g < 4; g++) { LDM4(Bhf[g], cb + 16384 + bOff[g]); }

#pragma unroll
            for (int i = 0; i < 2; i++)
#pragma unroll
                for (int j = 0; j < 8; j++) {
                    const uint32_t* bg = Bhf[j >> 1] + ((j & 1) << 1);
                    MMA_F16(acc[i][j], Ahf[i], bg[0], bg[1]);
                }
#pragma unroll
            for (int i = 0; i < 2; i++)
#pragma unroll
                for (int j = 0; j < 8; j++) {
                    const uint32_t* bg = Bhf[j >> 1] + ((j & 1) << 1);
                    MMA_F16(acc[i][j], Alf[i], bg[0], bg[1]);
                }
        }

        if (pf) {
            *(uint4*)(gsm + so + sd0)         = va0;
            *(uint4*)(gsm + so + sd1)         = va1;
            *(uint4*)(gsm + so + 8192 + sd0)  = vl0;
            *(uint4*)(gsm + so + 8192 + sd1)  = vl1;
            *(uint4*)(gsm + so + 16384 + sd0) = vb0;
            *(uint4*)(gsm + so + 16384 + sd1) = vb1;
        }
        __syncthreads();
    }

    // ---- epilogues ----
    const int fr = lane >> 2;
    const int fc = (lane & 3) << 1;

    if (mode == 1) {                       // out-projection -> fp32 C
#pragma unroll
        for (int i = 0; i < 2; i++)
#pragma unroll
            for (int j = 0; j < 8; j++) {
                float* c0p = Cout + (size_t)(bm + wm + i * 16 + fr) * DMODEL
                               + bn + wn + j * 8 + fc;
                *(float2*)c0p                = make_float2(acc[i][j][0], acc[i][j][1]);
                *(float2*)(c0p + 8 * DMODEL) = make_float2(acc[i][j][2], acc[i][j][3]);
            }
    } else if (blockIdx.z == 0) {          // Q -> qh/ql, scale 0.125 folded
#pragma unroll
        for (int i = 0; i < 2; i++)
#pragma unroll
            for (int j = 0; j < 8; j++) {
                size_t r0a = (size_t)(bm + wm + i * 16 + fr) * DMODEL
                           + bn + wn + j * 8 + fc;
                uint32_t l_, h_;
                h_ = pk_hilo(acc[i][j][0] * 0.125f, acc[i][j][1] * 0.125f, l_);
                *(uint32_t*)(g_qh + r0a) = h_;
                *(uint32_t*)(g_ql + r0a) = l_;
                h_ = pk_hilo(acc[i][j][2] * 0.125f, acc[i][j][3] * 0.125f, l_);
                *(uint32_t*)(g_qh + r0a + 8 * DMODEL) = h_;
                *(uint32_t*)(g_ql + r0a + 8 * DMODEL) = l_;
            }
    } else if (blockIdx.z == 1) {          // K -> kh
#pragma unroll
        for (int i = 0; i < 2; i++)
#pragma unroll
            for (int j = 0; j < 8; j++) {
                size_t r0a = (size_t)(bm + wm + i * 16 + fr) * DMODEL
                           + bn + wn + j * 8 + fc;
                __half2 h0 = __floats2half2_rn(acc[i][j][0], acc[i][j][1]);
                __half2 h1 = __floats2half2_rn(acc[i][j][2], acc[i][j][3]);
                *(uint32_t*)(g_kh + r0a)              = *reinterpret_cast<uint32_t*>(&h0);
                *(uint32_t*)(g_kh + r0a + 8 * DMODEL) = *reinterpret_cast<uint32_t*>(&h1);
            }
    } else {                               // V -> vt transposed [b][h][dh][t]
#pragma unroll
        for (int i = 0; i < 2; i++)
#pragma unroll
            for (int j = 0; j < 8; j++) {
                int nn  = bn + wn + j * 8 + fc;
                int hh  = nn >> 6, dh = nn & 63;
                int row = bm + wm + i * 16 + fr;
                int bb  = row >> 11, t = row & 2047;
                __half* vbase = g_vt + ((size_t)(bb * NHEADS + hh) * DHEAD) * T_SEQ;
                vbase[(size_t)dh * T_SEQ + t]           = __float2half(acc[i][j][0]);
                vbase[(size_t)(dh + 1) * T_SEQ + t]     = __float2half(acc[i][j][1]);
                vbase[(size_t)dh * T_SEQ + t + 8]       = __float2half(acc[i][j][2]);
                vbase[(size_t)(dh + 1) * T_SEQ + t + 8] = __float2half(acc[i][j][3]);
            }
    }
}

// =========================================================================
// fp16 2-term flash attention + rotation/valve epilogue.
// All operands arrive pre-converted fp16 (Q pre-scaled hi/lo, K hi, V^T hi):
// staging = pure vector LDG/STS. Output written as fp16 hi/lo for out-proj.
// =========================================================================
#define AT_QH 0
#define AT_QL 16384
#define AT_KV 32768
#define KV_STRIDE 16384    // per buffer: KH 0 | VH 8192
#define ATTN_SMEM 65536

__global__ __launch_bounds__(256)
void attn_mma(const float* __restrict__ beta_, const float* __restrict__ inval,
              const float* __restrict__ outval, const float* __restrict__ chiv)
{
    extern __shared__ __align__(16) char smb[];

    const int h    = blockIdx.y;
    const int b    = blockIdx.z;
    const int q0   = blockIdx.x << 7;
    const int tid  = threadIdx.x;
    const int warp = tid >> 5;
    const int lane = tid & 31;
    const int wm   = warp << 4;

    const __half* qhB = g_qh + (size_t)(b * T_SEQ + q0) * DMODEL + h * DHEAD;
    const __half* qlB = g_ql + (size_t)(b * T_SEQ + q0) * DMODEL + h * DHEAD;
    const __half* kB  = g_kh + (size_t)(b * T_SEQ) * DMODEL + h * DHEAD;
    const __half* vB  = g_vt + (size_t)(b * NHEADS + h) * DHEAD * T_SEQ;

    // ---- stage Q hi/lo: [128 rows][64 dh] -> 4 chunks of [128][16] ----
#pragma unroll
    for (int i = 0; i < 4; i++) {
        int idx = tid + (i << 8);
        int row = idx >> 3;
        int q4  = idx & 7;
        uint32_t dst = ((uint32_t)(q4 >> 1) << 12) + qoff(row, q4 & 1);
        *(uint4*)(smb + AT_QH + dst) = *(const uint4*)(qhB + (size_t)row * DMODEL + q4 * 8);
        *(uint4*)(smb + AT_QL + dst) = *(const uint4*)(qlB + (size_t)row * DMODEL + q4 * 8);
    }

    // staging map for K/V tiles: idx = tid (+256): row=idx>>3, q4=idx&7
    const int srow = tid >> 3;
    const int sq4  = tid & 7;
    const uint32_t kvd0 = ((uint32_t)(sq4 >> 1) << 11) + qoff(srow,      sq4 & 1);
    const uint32_t kvd1 = ((uint32_t)(sq4 >> 1) << 11) + qoff(srow + 32, sq4 & 1);

    // ---- stage K/V tile 0 into buffer 0 ----
    *(uint4*)(smb + AT_KV + kvd0)        = *(const uint4*)(kB + (size_t)srow * DMODEL + sq4 * 8);
    *(uint4*)(smb + AT_KV + kvd1)        = *(const uint4*)(kB + (size_t)(srow + 32) * DMODEL + sq4 * 8);
    *(uint4*)(smb + AT_KV + 8192 + kvd0) = *(const uint4*)(vB + (size_t)srow * T_SEQ + sq4 * 8);
    *(uint4*)(smb + AT_KV + 8192 + kvd1) = *(const uint4*)(vB + (size_t)(srow + 32) * T_SEQ + sq4 * 8);
    __syncthreads();

    // ---- fragment smem addresses ----
    const uint32_t sbase = smem_u32(smb);
    uint32_t aOffQ[4], bOff[4];
    {
        int r  = (lane & 7) + ((lane >> 3) & 1) * 8;
        int hA = (lane >> 4) & 1;
#pragma unroll
        for (int c = 0; c < 4; c++)
            aOffQ[c] = ((uint32_t)c << 12) + qoff(wm + r, hA);
        int rn_ = (lane & 7) + ((lane >> 4) & 1) * 8;
        int hB  = (lane >> 3) & 1;
#pragma unroll
        for (int g = 0; g < 4; g++)
            bOff[g] = qoff(16 * g + rn_, hB);
    }

    // ---- resident Q fragments ----
    uint32_t Qh[4][4], Ql[4][4];
#pragma unroll
    for (int c = 0; c < 4; c++) {
        LDM4(Qh[c], sbase + AT_QH + aOffQ[c]);
        LDM4(Ql[c], sbase + AT_QL + aOffQ[c]);
    }

    float o[8][4];
#pragma unroll
    for (int j = 0; j < 8; j++)
#pragma unroll
        for (int e = 0; e < 4; e++) o[j][e] = 0.f;
    float m0 = -1e30f, m1 = -1e30f, l0 = 0.f, l1 = 0.f;

    for (int kt = 0; kt < T_SEQ / 64; kt++) {
        const uint32_t bo = AT_KV + ((uint32_t)(kt & 1)) * KV_STRIDE;
        const uint32_t so = AT_KV + ((uint32_t)((kt & 1) ^ 1)) * KV_STRIDE;
        const bool pf = (kt < T_SEQ / 64 - 1);

        // ---- prefetch next tile (4 vector loads; overlaps MMA) ----
        uint4 k0, k1, v0, v1;
        if (pf) {
            const __half* kbt = kB + (size_t)(kt + 1) * 64 * DMODEL;
            const __half* vbt = vB + (size_t)(kt + 1) * 64;
            k0 = *(const uint4*)(kbt + (size_t)srow * DMODEL + sq4 * 8);
            k1 = *(const uint4*)(kbt + (size_t)(srow + 32) * DMODEL + sq4 * 8);
            v0 = *(const uint4*)(vbt + (size_t)srow * T_SEQ + sq4 * 8);
            v1 = *(const uint4*)(vbt + (size_t)(srow + 32) * T_SEQ + sq4 * 8);
        }

        // ---- S = (Q/8) K^T ----
        float s[8][4];
#pragma unroll
        for (int j = 0; j < 8; j++)
#pragma unroll
            for (int e = 0; e < 4; e++) s[j][e] = 0.f;

#pragma unroll
        for (int c = 0; c < 4; c++) {
            uint32_t Kh_[4][4];
#pragma unroll
            for (int g = 0; g < 4; g++) {
                LDM4(Kh_[g], sbase + bo + ((uint32_t)c << 11) + bOff[g]);
            }
#pragma unroll
            for (int j = 0; j < 8; j++) {
                const uint32_t* bg = Kh_[j >> 1] + ((j & 1) << 1);
                MMA_F16(s[j], Qh[c], bg[0], bg[1]);
            }
#pragma unroll
            for (int j = 0; j < 8; j++) {
                const uint32_t* bg = Kh_[j >> 1] + ((j & 1) << 1);
                MMA_F16(s[j], Ql[c], bg[0], bg[1]);
            }
        }

        // ---- online softmax ----
        float mx0 = -1e30f, mx1 = -1e30f;
#pragma unroll
        for (int j = 0; j < 8; j++) {
            mx0 = fmaxf(mx0, fmaxf(s[j][0], s[j][1]));
            mx1 = fmaxf(mx1, fmaxf(s[j][2], s[j][3]));
        }
        mx0 = fmaxf(mx0, __shfl_xor_sync(0xffffffffu, mx0, 1));
        mx0 = fmaxf(mx0, __shfl_xor_sync(0xffffffffu, mx0, 2));
        mx1 = fmaxf(mx1, __shfl_xor_sync(0xffffffffu, mx1, 1));
        mx1 = fmaxf(mx1, __shfl_xor_sync(0xffffffffu, mx1, 2));
        float nm0 = fmaxf(m0, mx0), nm1 = fmaxf(m1, mx1);
        float al0 = __expf(m0 - nm0), al1 = __expf(m1 - nm1);
        m0 = nm0; m1 = nm1;
        float ps0 = 0.f, ps1 = 0.f;
#pragma unroll
        for (int j = 0; j < 8; j++) {
            s[j][0] = __expf(s[j][0] - nm0);
            s[j][1] = __expf(s[j][1] - nm0);
            s[j][2] = __expf(s[j][2] - nm1);
            s[j][3] = __expf(s[j][3] - nm1);
            ps0 += s[j][0] + s[j][1];
            ps1 += s[j][2] + s[j][3];
        }
        ps0 += __shfl_xor_sync(0xffffffffu, ps0, 1);
        ps0 += __shfl_xor_sync(0xffffffffu, ps0, 2);
        ps1 += __shfl_xor_sync(0xffffffffu, ps1, 1);
        ps1 += __shfl_xor_sync(0xffffffffu, ps1, 2);
        l0 = l0 * al0 + ps0;
        l1 = l1 * al1 + ps1;
#pragma unroll
        for (int j = 0; j < 8; j++) {
            o[j][0] *= al0; o[j][1] *= al0;
            o[j][2] *= al1; o[j][3] *= al1;
        }

        // ---- O += P V (P hi/lo packed in registers) ----
#pragma unroll
        for (int c = 0; c < 4; c++) {
            uint32_t ph[4], pl[4];
            ph[0] = pk_hilo(s[2 * c][0],     s[2 * c][1],     pl[0]);
            ph[1] = pk_hilo(s[2 * c][2],     s[2 * c][3],     pl[1]);
            ph[2] = pk_hilo(s[2 * c + 1][0], s[2 * c + 1][1], pl[2]);
            ph[3] = pk_hilo(s[2 * c + 1][2], s[2 * c + 1][3], pl[3]);

            uint32_t Vh_[4][4];
#pragma unroll
            for (int g = 0; g < 4; g++) {
                LDM4(Vh_[g], sbase + bo + 8192 + ((uint32_t)c << 11) + bOff[g]);
            }
#pragma unroll
            for (int j = 0; j < 8; j++) {
                const uint32_t* bg = Vh_[j >> 1] + ((j & 1) << 1);
                MMA_F16(o[j], ph, bg[0], bg[1]);
            }
#pragma unroll
            for (int j = 0; j < 8; j++) {
                const uint32_t* bg = Vh_[j >> 1] + ((j & 1) << 1);
                MMA_F16(o[j], pl, bg[0], bg[1]);
            }
        }

        // ---- stage prefetched tile into other buffer ----
        if (pf) {
            *(uint4*)(smb + so + kvd0)        = k0;
            *(uint4*)(smb + so + kvd1)        = k1;
            *(uint4*)(smb + so + 8192 + kvd0) = v0;
            *(uint4*)(smb + so + 8192 + kvd1) = v1;
        }
        __syncthreads();
    }

    // ---- per-head constants ----
    float bsig = 1.f / (1.f + expf(-beta_[h]));
    float sa, ca;
    sincosf(PI_F * bsig, &sa, &ca);
    float iv  = 1.f / (1.f + expf(-inval[h]));
    float ov  = 1.f / (1.f + expf(-outval[h]));
    float gch = tanhf(chiv[h]);
    float fac = iv * ov * gch;

    // ---- normalize, rotate, write fp16 hi/lo for the out-projection ----
    const float inv0 = 1.f / l0, inv1 = 1.f / l1;
    const int   fr   = lane >> 2;
    const int   fc   = (lane & 3) << 1;
    const size_t rbase = (size_t)(b * T_SEQ + q0 + wm + fr) * DMODEL + h * DHEAD;
#pragma unroll
    for (int j = 0; j < 4; j++) {
        uint32_t l_, h_;
        float xr0 = o[j][0] * inv0,     xr1 = o[j][1] * inv0;
        float xi0 = o[j + 4][0] * inv0, xi1 = o[j + 4][1] * inv0;
        h_ = pk_hilo((xr0 * ca - xi0 * sa) * fac, (xr1 * ca - xi1 * sa) * fac, l_);
        *(uint32_t*)(g_aoh + rbase + 8 * j + fc) = h_;
        *(uint32_t*)(g_aol + rbase + 8 * j + fc) = l_;
        h_ = pk_hilo((xr0 * sa + xi0 * ca) * fac, (xr1 * sa + xi1 * ca) * fac, l_);
        *(uint32_t*)(g_aoh + rbase + 8 * j + fc + 32) = h_;
        *(uint32_t*)(g_aol + rbase + 8 * j + fc + 32) = l_;

        float yr0 = o[j][2] * inv1,     yr1 = o[j][3] * inv1;
        float yi0 = o[j + 4][2] * inv1, yi1 = o[j + 4][3] * inv1;
        h_ = pk_hilo((yr0 * ca - yi0 * sa) * fac, (yr1 * ca - yi1 * sa) * fac, l_);
        *(uint32_t*)(g_aoh + rbase + 8 * DMODEL + 8 * j + fc) = h_;
        *(uint32_t*)(g_aol + rbase + 8 * DMODEL + 8 * j + fc) = l_;
        h_ = pk_hilo((yr0 * sa + yi0 * ca) * fac, (yr1 * sa + yi1 * ca) * fac, l_);
        *(uint32_t*)(g_aoh + rbase + 8 * DMODEL + 8 * j + fc + 32) = h_;
        *(uint32_t*)(g_aol + rbase + 8 * DMODEL + 8 * j + fc + 32) = l_;
    }
}

// =========================================================================
extern "C" void kernel_launch(void* const* d_in, const int* in_sizes, int n_in,
                              void* d_out, int out_size)
{
    (void)in_sizes; (void)n_in; (void)out_size;

    const float* x    = (const float*)d_in[0];
    const float* Wq   = (const float*)d_in[1];
    const float* Wk   = (const float*)d_in[2];
    const float* Wv   = (const float*)d_in[3];
    const float* We   = (const float*)d_in[4];
    const float* beta = (const float*)d_in[5];
    const float* ivv  = (const float*)d_in[6];
    const float* ovv  = (const float*)d_in[7];
    const float* chi  = (const float*)d_in[8];
    float* out = (float*)d_out;

    __half *xh, *xl, *wqh, *wkh, *wvh, *weh, *aoh, *aol;
    cudaGetSymbolAddress((void**)&xh,  g_xh);
    cudaGetSymbolAddress((void**)&xl,  g_xl);
    cudaGetSymbolAddress((void**)&wqh, g_wqh);
    cudaGetSymbolAddress((void**)&wkh, g_wkh);
    cudaGetSymbolAddress((void**)&wvh, g_wvh);
    cudaGetSymbolAddress((void**)&weh, g_weh);
    cudaGetSymbolAddress((void**)&aoh, g_aoh);
    cudaGetSymbolAddress((void**)&aol, g_aol);

    cudaFuncSetAttribute(gemm_h, cudaFuncAttributeMaxDynamicSharedMemorySize,
                         GEMM_SMEM);
    cudaFuncSetAttribute(attn_mma, cudaFuncAttributeMaxDynamicSharedMemorySize,
                         ATTN_SMEM);

    preconvert<<<1024, 256>>>(x, Wq, Wk, Wv, We);

    dim3 gqkv(DMODEL / 128, MROWS / 128, 3);   // fused Q/K/V projections
    gemm_h<<<gqkv, 256, GEMM_SMEM>>>(xh, xl, wqh, wkh, wvh, nullptr, 0);

    dim3 ga(T_SEQ / 128, NHEADS, BATCH);       // (16, 16, 2)
    attn_mma<<<ga, 256, ATTN_SMEM>>>(beta, ivv, ovv, chi);

    dim3 go(DMODEL / 128, MROWS / 128, 1);     // output projection
    gemm_h<<<go, 256, GEMM_SMEM>>>(aoh, aol, weh, weh, weh, out, 1);
}

// round 17
// speedup vs baseline: 1.1641x; 1.1641x over previous
#include <cuda_runtime.h>
#include <cuda_fp16.h>
#include <math.h>
#include <stdint.h>

#define T_SEQ   2048
#define BATCH   2
#define DMODEL  1024
#define NHEADS  16
#define DHEAD   64
#define MROWS   (BATCH * T_SEQ)   // 4096
#define PI_F    3.14159265358979323846f

// ---------------- device scratch (fp16 end-to-end dataflow) --------------
__device__ __half g_xh [MROWS * DMODEL];
__device__ __half g_xl [MROWS * DMODEL];
__device__ __half g_wqh[DMODEL * DMODEL];
__device__ __half g_wkh[DMODEL * DMODEL];
__device__ __half g_wvh[DMODEL * DMODEL];
__device__ __half g_weh[DMODEL * DMODEL];
__device__ __half g_qh [MROWS * DMODEL];
__device__ __half g_ql [MROWS * DMODEL];
__device__ __half g_kh [MROWS * DMODEL];
__device__ __half g_vt [BATCH * NHEADS * DHEAD * T_SEQ];  // v^T [b][h][dh][t]
__device__ __half g_aoh[MROWS * DMODEL];
__device__ __half g_aol[MROWS * DMODEL];

// =========================================================================
// helpers
// =========================================================================
__device__ __forceinline__ uint32_t smem_u32(const void* p) {
    uint32_t a;
    asm("{ .reg .u64 t; cvta.to.shared.u64 t, %1; cvt.u32.u64 %0, t; }"
        : "=r"(a) : "l"(p));
    return a;
}

__device__ __forceinline__ uint32_t qoff(int row, int half) {
    return (uint32_t)((((row >> 3) << 4) + ((row & 7) << 1) +
                       (half ^ ((row >> 2) & 1))) << 4);
}

#define LDM4(r, addr) \
    asm volatile("ldmatrix.sync.aligned.m8n8.x4.shared.b16 {%0,%1,%2,%3}, [%4];" \
        : "=r"((r)[0]), "=r"((r)[1]), "=r"((r)[2]), "=r"((r)[3]) : "r"(addr))

#define MMA_F16(d, a, b0_, b1_) \
    asm volatile("mma.sync.aligned.m16n8k16.row.col.f32.f16.f16.f32 " \
        "{%0,%1,%2,%3},{%4,%5,%6,%7},{%8,%9},{%0,%1,%2,%3};" \
        : "+f"((d)[0]), "+f"((d)[1]), "+f"((d)[2]), "+f"((d)[3]) \
        : "r"((a)[0]), "r"((a)[1]), "r"((a)[2]), "r"((a)[3]), \
          "r"(b0_), "r"(b1_))

#define CPA16(dst, src) \
    asm volatile("cp.async.ca.shared.global [%0], [%1], 16;" \
        :: "r"(dst), "l"(src) : "memory")
#define CPA_COMMIT() asm volatile("cp.async.commit_group;" ::: "memory")
#define CPA_WAIT(n)  asm volatile("cp.async.wait_group %0;" :: "n"(n) : "memory")

__device__ __forceinline__ void cvt_hilo(float4 v, uint2& hi, uint2& lo) {
    __half2 h01 = __floats2half2_rn(v.x, v.y);
    __half2 h23 = __floats2half2_rn(v.z, v.w);
    float2 f01 = __half22float2(h01);
    float2 f23 = __half22float2(h23);
    __half2 l01 = __floats2half2_rn(v.x - f01.x, v.y - f01.y);
    __half2 l23 = __floats2half2_rn(v.z - f23.x, v.w - f23.y);
    hi.x = *reinterpret_cast<unsigned*>(&h01);
    hi.y = *reinterpret_cast<unsigned*>(&h23);
    lo.x = *reinterpret_cast<unsigned*>(&l01);
    lo.y = *reinterpret_cast<unsigned*>(&l23);
}

__device__ __forceinline__ uint2 cvt_hi(float4 v) {
    __half2 h01 = __floats2half2_rn(v.x, v.y);
    __half2 h23 = __floats2half2_rn(v.z, v.w);
    uint2 hi;
    hi.x = *reinterpret_cast<unsigned*>(&h01);
    hi.y = *reinterpret_cast<unsigned*>(&h23);
    return hi;
}

__device__ __forceinline__ uint32_t pk_hilo(float a, float b, uint32_t& lo) {
    __half2 h = __floats2half2_rn(a, b);
    float2 f = __half22float2(h);
    __half2 l = __floats2half2_rn(a - f.x, b - f.y);
    lo = *reinterpret_cast<uint32_t*>(&l);
    return *reinterpret_cast<uint32_t*>(&h);
}

// =========================================================================
// one-time fp32 -> fp16 conversion (memory-bound, ~15 us)
// =========================================================================
__global__ __launch_bounds__(256)
void preconvert(const float* __restrict__ x,  const float* __restrict__ wq,
                const float* __restrict__ wk, const float* __restrict__ wv,
                const float* __restrict__ we)
{
    const int gt = blockIdx.x * 256 + threadIdx.x;
    const int G  = gridDim.x * 256;
    const int NX = MROWS * DMODEL / 4;
    for (int i = gt; i < NX; i += G) {
        uint2 hi, lo;
        cvt_hilo(((const float4*)x)[i], hi, lo);
        ((uint2*)g_xh)[i] = hi;
        ((uint2*)g_xl)[i] = lo;
    }
    const int NW = DMODEL * DMODEL / 4;
    for (int i = gt; i < NW; i += G) {
        ((uint2*)g_wqh)[i] = cvt_hi(((const float4*)wq)[i]);
        ((uint2*)g_wkh)[i] = cvt_hi(((const float4*)wk)[i]);
        ((uint2*)g_wvh)[i] = cvt_hi(((const float4*)wv)[i]);
        ((uint2*)g_weh)[i] = cvt_hi(((const float4*)we)[i]);
    }
}

// =========================================================================
// fp16 2-term GEMM (NT): C = Ah*Bh + Al*Bh, BK=32, 3-stage cp.async
// pipeline (zero staging registers), one barrier per chunk.
// mode 0: QKV epilogues (z: Q->qh/ql scaled | K->kh | V->vt^T)
// mode 1: out-projection -> fp32 C
// =========================================================================
#define GSTG 24576                    // per-stage: Ah 8K | Al 8K | Bh 8K
#define GEMM_SMEM (3 * GSTG)          // 73,728 B

__global__ __launch_bounds__(256, 2)
void gemm_h(const __half* __restrict__ Ah, const __half* __restrict__ Al,
            const __half* __restrict__ B0, const __half* __restrict__ B1,
            const __half* __restrict__ B2, float* __restrict__ Cout, int mode)
{
    extern __shared__ __align__(16) char gsm[];

    const __half* Bh = (blockIdx.z == 0) ? B0 : (blockIdx.z == 1) ? B1 : B2;

    const int tid  = threadIdx.x;
    const int warp = tid >> 5;
    const int lane = tid & 31;
    const int wm   = (warp & 3) << 5;
    const int wn   = (warp >> 2) << 6;
    const int bm   = blockIdx.y << 7;
    const int bn   = blockIdx.x << 7;

    // staging map: thread -> (row r0s / r0s+64, 16B quad q4s of 32-k chunk)
    const int r0s = tid >> 2;
    const int q4s = tid & 3;
    const uint32_t sd0 = ((uint32_t)(q4s >> 1) << 12) + qoff(r0s,      q4s & 1);
    const uint32_t sd1 = ((uint32_t)(q4s >> 1) << 12) + qoff(r0s + 64, q4s & 1);

    const uint32_t sb = smem_u32(gsm);

    const __half* pA0 = Ah + (size_t)(bm + r0s) * DMODEL + q4s * 8;
    const __half* pL0 = Al + (size_t)(bm + r0s) * DMODEL + q4s * 8;
    const __half* pB0 = Bh + (size_t)(bn + r0s) * DMODEL + q4s * 8;

    uint32_t aOff[2], bOff[4];
    {
        int r  = (lane & 7) + ((lane >> 3) & 1) * 8;
        int hA = (lane >> 4) & 1;
        aOff[0] = qoff(wm + r,      hA);
        aOff[1] = qoff(wm + 16 + r, hA);
        int rn_ = (lane & 7) + ((lane >> 4) & 1) * 8;
        int hB  = (lane >> 3) & 1;
#pragma unroll
        for (int j = 0; j < 4; j++)
            bOff[j] = qoff(wn + 16 * j + rn_, hB);
    }

    float acc[2][8][4];
#pragma unroll
    for (int i = 0; i < 2; i++)
#pragma unroll
        for (int j = 0; j < 8; j++)
#pragma unroll
            for (int e = 0; e < 4; e++) acc[i][j][e] = 0.f;

    const int NC = DMODEL / 32;       // 32 chunks

    // ---- issue stages 0 and 1 ----
#pragma unroll
    for (int p = 0; p < 2; p++) {
        const uint32_t st = sb + p * GSTG;
        const int koff = p * 32;
        CPA16(st + sd0,           pA0 + koff);
        CPA16(st + sd1,           pA0 + koff + 64 * DMODEL);
        CPA16(st + 8192 + sd0,    pL0 + koff);
        CPA16(st + 8192 + sd1,    pL0 + koff + 64 * DMODEL);
        CPA16(st + 16384 + sd0,   pB0 + koff);
        CPA16(st + 16384 + sd1,   pB0 + koff + 64 * DMODEL);
        CPA_COMMIT();
    }

    int stg = 0;                      // stage index of chunk c
    for (int c = 0; c < NC; c++) {
        if (c + 2 < NC) { CPA_WAIT(1); } else { CPA_WAIT(0); }
        __syncthreads();

        if (c + 2 < NC) {
            int ns = stg + 2; if (ns >= 3) ns -= 3;
            const uint32_t st = sb + ns * GSTG;
            const int koff = (c + 2) * 32;
            CPA16(st + sd0,           pA0 + koff);
            CPA16(st + sd1,           pA0 + koff + 64 * DMODEL);
            CPA16(st + 8192 + sd0,    pL0 + koff);
            CPA16(st + 8192 + sd1,    pL0 + koff + 64 * DMODEL);
            CPA16(st + 16384 + sd0,   pB0 + koff);
            CPA16(st + 16384 + sd1,   pB0 + koff + 64 * DMODEL);
            CPA_COMMIT();
        }

        const uint32_t base = sb + stg * GSTG;
#pragma unroll
        for (int s = 0; s < 2; s++) {
            const uint32_t cb = base + ((uint32_t)s << 12);
            uint32_t Ahf[2][4], Alf[2][4], Bhf[4][4];
            LDM4(Ahf[0], cb + aOff[0]);          LDM4(Ahf[1], cb + aOff[1]);
            LDM4(Alf[0], cb + 8192 + aOff[0]);   LDM4(Alf[1], cb + 8192 + aOff[1]);
#pragma unroll
            for (int g = 0; g < 4; g++) { LDM4(Bhf[g], cb + 16384 + bOff[g]); }

#pragma unroll
            for (int i = 0; i < 2; i++)
#pragma unroll
                for (int j = 0; j < 8; j++) {
                    const uint32_t* bg = Bhf[j >> 1] + ((j & 1) << 1);
                    MMA_F16(acc[i][j], Ahf[i], bg[0], bg[1]);
                }
#pragma unroll
            for (int i = 0; i < 2; i++)
#pragma unroll
                for (int j = 0; j < 8; j++) {
                    const uint32_t* bg = Bhf[j >> 1] + ((j & 1) << 1);
                    MMA_F16(acc[i][j], Alf[i], bg[0], bg[1]);
                }
        }
        if (++stg == 3) stg = 0;
    }

    // ---- epilogues ----
    const int fr = lane >> 2;
    const int fc = (lane & 3) << 1;

    if (mode == 1) {                       // out-projection -> fp32 C
#pragma unroll
        for (int i = 0; i < 2; i++)
#pragma unroll
            for (int j = 0; j < 8; j++) {
                float* c0p = Cout + (size_t)(bm + wm + i * 16 + fr) * DMODEL
                               + bn + wn + j * 8 + fc;
                *(float2*)c0p                = make_float2(acc[i][j][0], acc[i][j][1]);
                *(float2*)(c0p + 8 * DMODEL) = make_float2(acc[i][j][2], acc[i][j][3]);
            }
    } else if (blockIdx.z == 0) {          // Q -> qh/ql, scale 0.125 folded
#pragma unroll
        for (int i = 0; i < 2; i++)
#pragma unroll
            for (int j = 0; j < 8; j++) {
                size_t r0a = (size_t)(bm + wm + i * 16 + fr) * DMODEL
                           + bn + wn + j * 8 + fc;
                uint32_t l_, h_;
                h_ = pk_hilo(acc[i][j][0] * 0.125f, acc[i][j][1] * 0.125f, l_);
                *(uint32_t*)(g_qh + r0a) = h_;
                *(uint32_t*)(g_ql + r0a) = l_;
                h_ = pk_hilo(acc[i][j][2] * 0.125f, acc[i][j][3] * 0.125f, l_);
                *(uint32_t*)(g_qh + r0a + 8 * DMODEL) = h_;
                *(uint32_t*)(g_ql + r0a + 8 * DMODEL) = l_;
            }
    } else if (blockIdx.z == 1) {          // K -> kh
#pragma unroll
        for (int i = 0; i < 2; i++)
#pragma unroll
            for (int j = 0; j < 8; j++) {
                size_t r0a = (size_t)(bm + wm + i * 16 + fr) * DMODEL
                           + bn + wn + j * 8 + fc;
                __half2 h0 = __floats2half2_rn(acc[i][j][0], acc[i][j][1]);
                __half2 h1 = __floats2half2_rn(acc[i][j][2], acc[i][j][3]);
                *(uint32_t*)(g_kh + r0a)              = *reinterpret_cast<uint32_t*>(&h0);
                *(uint32_t*)(g_kh + r0a + 8 * DMODEL) = *reinterpret_cast<uint32_t*>(&h1);
            }
    } else {                               // V -> vt transposed [b][h][dh][t]
#pragma unroll
        for (int i = 0; i < 2; i++)
#pragma unroll
            for (int j = 0; j < 8; j++) {
                int nn  = bn + wn + j * 8 + fc;
                int hh  = nn >> 6, dh = nn & 63;
                int row = bm + wm + i * 16 + fr;
                int bb  = row >> 11, t = row & 2047;
                __half* vbase = g_vt + ((size_t)(bb * NHEADS + hh) * DHEAD) * T_SEQ;
                vbase[(size_t)dh * T_SEQ + t]           = __float2half(acc[i][j][0]);
                vbase[(size_t)(dh + 1) * T_SEQ + t]     = __float2half(acc[i][j][1]);
                vbase[(size_t)dh * T_SEQ + t + 8]       = __float2half(acc[i][j][2]);
                vbase[(size_t)(dh + 1) * T_SEQ + t + 8] = __float2half(acc[i][j][3]);
            }
    }
}

// =========================================================================
// fp16 2-term flash attention + rotation/valve epilogue.
// K/V tiles staged by a 3-stage cp.async pipeline (zero staging registers),
// one barrier per tile. Q fragments register-resident. fp16 hi/lo output.
// =========================================================================
#define AT_QH 0
#define AT_QL 16384
#define AT_KV 32768
#define KV_STRIDE 16384               // per stage: KH 0 | VH 8192
#define ATTN_SMEM (32768 + 3 * KV_STRIDE)   // 81,920 B

__global__ __launch_bounds__(256)
void attn_mma(const float* __restrict__ beta_, const float* __restrict__ inval,
              const float* __restrict__ outval, const float* __restrict__ chiv)
{
    extern __shared__ __align__(16) char smb[];

    const int h    = blockIdx.y;
    const int b    = blockIdx.z;
    const int q0   = blockIdx.x << 7;
    const int tid  = threadIdx.x;
    const int warp = tid >> 5;
    const int lane = tid & 31;
    const int wm   = warp << 4;

    const __half* qhB = g_qh + (size_t)(b * T_SEQ + q0) * DMODEL + h * DHEAD;
    const __half* qlB = g_ql + (size_t)(b * T_SEQ + q0) * DMODEL + h * DHEAD;
    const __half* kB  = g_kh + (size_t)(b * T_SEQ) * DMODEL + h * DHEAD;
    const __half* vB  = g_vt + (size_t)(b * NHEADS + h) * DHEAD * T_SEQ;

    const uint32_t sbase = smem_u32(smb);

    // staging map: idx = tid: row = idx>>3 (0..31, +32), q4 = idx&7
    const int srow = tid >> 3;
    const int sq4  = tid & 7;
    const uint32_t kvd0 = ((uint32_t)(sq4 >> 1) << 11) + qoff(srow,      sq4 & 1);
    const uint32_t kvd1 = ((uint32_t)(sq4 >> 1) << 11) + qoff(srow + 32, sq4 & 1);

    // ---- issue K/V tiles 0 and 1 via cp.async ----
#pragma unroll
    for (int p = 0; p < 2; p++) {
        const uint32_t st = sbase + AT_KV + p * KV_STRIDE;
        const __half* kbt = kB + (size_t)p * 64 * DMODEL;
        const __half* vbt = vB + (size_t)p * 64;
        CPA16(st + kvd0,        kbt + (size_t)srow * DMODEL + sq4 * 8);
        CPA16(st + kvd1,        kbt + (size_t)(srow + 32) * DMODEL + sq4 * 8);
        CPA16(st + 8192 + kvd0, vbt + (size_t)srow * T_SEQ + sq4 * 8);
        CPA16(st + 8192 + kvd1, vbt + (size_t)(srow + 32) * T_SEQ + sq4 * 8);
        CPA_COMMIT();
    }

    // ---- stage Q hi/lo (regular stores, overlaps the cp.asyncs) ----
#pragma unroll
    for (int i = 0; i < 4; i++) {
        int idx = tid + (i << 8);
        int row = idx >> 3;
        int q4  = idx & 7;
        uint32_t dst = ((uint32_t)(q4 >> 1) << 12) + qoff(row, q4 & 1);
        *(uint4*)(smb + AT_QH + dst) = *(const uint4*)(qhB + (size_t)row * DMODEL + q4 * 8);
        *(uint4*)(smb + AT_QL + dst) = *(const uint4*)(qlB + (size_t)row * DMODEL + q4 * 8);
    }
    __syncthreads();

    uint32_t aOffQ[4], bOff[4];
    {
        int r  = (lane & 7) + ((lane >> 3) & 1) * 8;
        int hA = (lane >> 4) & 1;
#pragma unroll
        for (int c = 0; c < 4; c++)
            aOffQ[c] = ((uint32_t)c << 12) + qoff(wm + r, hA);
        int rn_ = (lane & 7) + ((lane >> 4) & 1) * 8;
        int hB  = (lane >> 3) & 1;
#pragma unroll
        for (int g = 0; g < 4; g++)
            bOff[g] = qoff(16 * g + rn_, hB);
    }

    uint32_t Qh[4][4], Ql[4][4];
#pragma unroll
    for (int c = 0; c < 4; c++) {
        LDM4(Qh[c], sbase + AT_QH + aOffQ[c]);
        LDM4(Ql[c], sbase + AT_QL + aOffQ[c]);
    }

    float o[8][4];
#pragma unroll
    for (int j = 0; j < 8; j++)
#pragma unroll
        for (int e = 0; e < 4; e++) o[j][e] = 0.f;
    float m0 = -1e30f, m1 = -1e30f, l0 = 0.f, l1 = 0.f;

    const int NT = T_SEQ / 64;        // 32 tiles
    int stg = 0;
    for (int kt = 0; kt < NT; kt++) {
        if (kt + 2 < NT) { CPA_WAIT(1); } else { CPA_WAIT(0); }
        __syncthreads();

        if (kt + 2 < NT) {
            int ns = stg + 2; if (ns >= 3) ns -= 3;
            const uint32_t st = sbase + AT_KV + ns * KV_STRIDE;
            const __half* kbt = kB + (size_t)(kt + 2) * 64 * DMODEL;
            const __half* vbt = vB + (size_t)(kt + 2) * 64;
            CPA16(st + kvd0,        kbt + (size_t)srow * DMODEL + sq4 * 8);
            CPA16(st + kvd1,        kbt + (size_t)(srow + 32) * DMODEL + sq4 * 8);
            CPA16(st + 8192 + kvd0, vbt + (size_t)srow * T_SEQ + sq4 * 8);
            CPA16(st + 8192 + kvd1, vbt + (size_t)(srow + 32) * T_SEQ + sq4 * 8);
            CPA_COMMIT();
        }

        const uint32_t bo = sbase + AT_KV + stg * KV_STRIDE;

        // ---- S = (Q/8) K^T ----
        float s[8][4];
#pragma unroll
        for (int j = 0; j < 8; j++)
#pragma unroll
            for (int e = 0; e < 4; e++) s[j][e] = 0.f;

#pragma unroll
        for (int c = 0; c < 4; c++) {
            uint32_t Kh_[4][4];
#pragma unroll
            for (int g = 0; g < 4; g++) {
                LDM4(Kh_[g], bo + ((uint32_t)c << 11) + bOff[g]);
            }
#pragma unroll
            for (int j = 0; j < 8; j++) {
                const uint32_t* bg = Kh_[j >> 1] + ((j & 1) << 1);
                MMA_F16(s[j], Qh[c], bg[0], bg[1]);
            }
#pragma unroll
            for (int j = 0; j < 8; j++) {
                const uint32_t* bg = Kh_[j >> 1] + ((j & 1) << 1);
                MMA_F16(s[j], Ql[c], bg[0], bg[1]);
            }
        }

        // ---- online softmax ----
        float mx0 = -1e30f, mx1 = -1e30f;
#pragma unroll
        for (int j = 0; j < 8; j++) {
            mx0 = fmaxf(mx0, fmaxf(s[j][0], s[j][1]));
            mx1 = fmaxf(mx1, fmaxf(s[j][2], s[j][3]));
        }
        mx0 = fmaxf(mx0, __shfl_xor_sync(0xffffffffu, mx0, 1));
        mx0 = fmaxf(mx0, __shfl_xor_sync(0xffffffffu, mx0, 2));
        mx1 = fmaxf(mx1, __shfl_xor_sync(0xffffffffu, mx1, 1));
        mx1 = fmaxf(mx1, __shfl_xor_sync(0xffffffffu, mx1, 2));
        float nm0 = fmaxf(m0, mx0), nm1 = fmaxf(m1, mx1);
        float al0 = __expf(m0 - nm0), al1 = __expf(m1 - nm1);
        m0 = nm0; m1 = nm1;
        float ps0 = 0.f, ps1 = 0.f;
#pragma unroll
        for (int j = 0; j < 8; j++) {
            s[j][0] = __expf(s[j][0] - nm0);
            s[j][1] = __expf(s[j][1] - nm0);
            s[j][2] = __expf(s[j][2] - nm1);
            s[j][3] = __expf(s[j][3] - nm1);
            ps0 += s[j][0] + s[j][1];
            ps1 += s[j][2] + s[j][3];
        }
        ps0 += __shfl_xor_sync(0xffffffffu, ps0, 1);
        ps0 += __shfl_xor_sync(0xffffffffu, ps0, 2);
        ps1 += __shfl_xor_sync(0xffffffffu, ps1, 1);
        ps1 += __shfl_xor_sync(0xffffffffu, ps1, 2);
        l0 = l0 * al0 + ps0;
        l1 = l1 * al1 + ps1;
#pragma unroll
        for (int j = 0; j < 8; j++) {
            o[j][0] *= al0; o[j][1] *= al0;
            o[j][2] *= al1; o[j][3] *= al1;
        }

        // ---- O += P V ----
#pragma unroll
        for (int c = 0; c < 4; c++) {
            uint32_t ph[4], pl[4];
            ph[0] = pk_hilo(s[2 * c][0],     s[2 * c][1],     pl[0]);
            ph[1] = pk_hilo(s[2 * c][2],     s[2 * c][3],     pl[1]);
            ph[2] = pk_hilo(s[2 * c + 1][0], s[2 * c + 1][1], pl[2]);
            ph[3] = pk_hilo(s[2 * c + 1][2], s[2 * c + 1][3], pl[3]);

            uint32_t Vh_[4][4];
#pragma unroll
            for (int g = 0; g < 4; g++) {
                LDM4(Vh_[g], bo + 8192 + ((uint32_t)c << 11) + bOff[g]);
            }
#pragma unroll
            for (int j = 0; j < 8; j++) {
                const uint32_t* bg = Vh_[j >> 1] + ((j & 1) << 1);
                MMA_F16(o[j], ph, bg[0], bg[1]);
            }
#pragma unroll
            for (int j = 0; j < 8; j++) {
                const uint32_t* bg = Vh_[j >> 1] + ((j & 1) << 1);
                MMA_F16(o[j], pl, bg[0], bg[1]);
            }
        }

        if (++stg == 3) stg = 0;
    }

    // ---- per-head constants ----
    float bsig = 1.f / (1.f + expf(-beta_[h]));
    float sa, ca;
    sincosf(PI_F * bsig, &sa, &ca);
    float iv  = 1.f / (1.f + expf(-inval[h]));
    float ov  = 1.f / (1.f + expf(-outval[h]));
    float gch = tanhf(chiv[h]);
    float fac = iv * ov * gch;

    // ---- normalize, rotate, write fp16 hi/lo for the out-projection ----
    const float inv0 = 1.f / l0, inv1 = 1.f / l1;
    const int   fr   = lane >> 2;
    const int   fc   = (lane & 3) << 1;
    const size_t rbase = (size_t)(b * T_SEQ + q0 + wm + fr) * DMODEL + h * DHEAD;
#pragma unroll
    for (int j = 0; j < 4; j++) {
        uint32_t l_, h_;
        float xr0 = o[j][0] * inv0,     xr1 = o[j][1] * inv0;
        float xi0 = o[j + 4][0] * inv0, xi1 = o[j + 4][1] * inv0;
        h_ = pk_hilo((xr0 * ca - xi0 * sa) * fac, (xr1 * ca - xi1 * sa) * fac, l_);
        *(uint32_t*)(g_aoh + rbase + 8 * j + fc) = h_;
        *(uint32_t*)(g_aol + rbase + 8 * j + fc) = l_;
        h_ = pk_hilo((xr0 * sa + xi0 * ca) * fac, (xr1 * sa + xi1 * ca) * fac, l_);
        *(uint32_t*)(g_aoh + rbase + 8 * j + fc + 32) = h_;
        *(uint32_t*)(g_aol + rbase + 8 * j + fc + 32) = l_;

        float yr0 = o[j][2] * inv1,     yr1 = o[j][3] * inv1;
        float yi0 = o[j + 4][2] * inv1, yi1 = o[j + 4][3] * inv1;
        h_ = pk_hilo((yr0 * ca - yi0 * sa) * fac, (yr1 * ca - yi1 * sa) * fac, l_);
        *(uint32_t*)(g_aoh + rbase + 8 * DMODEL + 8 * j + fc) = h_;
        *(uint32_t*)(g_aol + rbase + 8 * DMODEL + 8 * j + fc) = l_;
        h_ = pk_hilo((yr0 * sa + yi0 * ca) * fac, (yr1 * sa + yi1 * ca) * fac, l_);
        *(uint32_t*)(g_aoh + rbase + 8 * DMODEL + 8 * j + fc + 32) = h_;
        *(uint32_t*)(g_aol + rbase + 8 * DMODEL + 8 * j + fc + 32) = l_;
    }
}

// =========================================================================
extern "C" void kernel_launch(void* const* d_in, const int* in_sizes, int n_in,
                              void* d_out, int out_size)
{
    (void)in_sizes; (void)n_in; (void)out_size;

    const float* x    = (const float*)d_in[0];
    const float* Wq   = (const float*)d_in[1];
    const float* Wk   = (const float*)d_in[2];
    const float* Wv   = (const float*)d_in[3];
    const float* We   = (const float*)d_in[4];
    const float* beta = (const float*)d_in[5];
    const float* ivv  = (const float*)d_in[6];
    const float* ovv  = (const float*)d_in[7];
    const float* chi  = (const float*)d_in[8];
    float* out = (float*)d_out;

    __half *xh, *xl, *wqh, *wkh, *wvh, *weh, *aoh, *aol;
    cudaGetSymbolAddress((void**)&xh,  g_xh);
    cudaGetSymbolAddress((void**)&xl,  g_xl);
    cudaGetSymbolAddress((void**)&wqh, g_wqh);
    cudaGetSymbolAddress((void**)&wkh, g_wkh);
    cudaGetSymbolAddress((void**)&wvh, g_wvh);
    cudaGetSymbolAddress((void**)&weh, g_weh);
    cudaGetSymbolAddress((void**)&aoh, g_aoh);
    cudaGetSymbolAddress((void**)&aol, g_aol);

    cudaFuncSetAttribute(gemm_h, cudaFuncAttributeMaxDynamicSharedMemorySize,
                         GEMM_SMEM);
    cudaFuncSetAttribute(attn_mma, cudaFuncAttributeMaxDynamicSharedMemorySize,
                         ATTN_SMEM);

    preconvert<<<1024, 256>>>(x, Wq, Wk, Wv, We);

    dim3 gqkv(DMODEL / 128, MROWS / 128, 3);   // fused Q/K/V projections
    gemm_h<<<gqkv, 256, GEMM_SMEM>>>(xh, xl, wqh, wkh, wvh, nullptr, 0);

    dim3 ga(T_SEQ / 128, NHEADS, BATCH);       // (16, 16, 2)
    attn_mma<<<ga, 256, ATTN_SMEM>>>(beta, ivv, ovv, chi);

    dim3 go(DMODEL / 128, MROWS / 128, 1);     // output projection
    gemm_h<<<go, 256, GEMM_SMEM>>>(aoh, aol, weh, weh, weh, out, 1);
}